// round 10
// baseline (speedup 1.0000x reference)
#include <cuda_runtime.h>

// MultiHeadAttention: B=4096, S=102, HIDDEN=8, HEADS=2, HEAD_DIM=4
// NB=4 batches/CTA (224 thr), QB=4 queries/thread, conflict-free interleaved
// K/V smem layout, packed f32x2 math, qs reused as attention-output buffer.

#define SQ   102
#define NB   4
#define NT   224
#define KVST (SQ * 16 + 8)   // 1640 floats per batch: stride mod 32 = 8 -> bank-spread

typedef unsigned long long u64;

__device__ __forceinline__ u64 pack2(float lo, float hi) {
    u64 r; asm("mov.b64 %0, {%1, %2};" : "=l"(r) : "f"(lo), "f"(hi)); return r;
}
__device__ __forceinline__ void unpack2(u64 v, float& lo, float& hi) {
    asm("mov.b64 {%0, %1}, %2;" : "=f"(lo), "=f"(hi) : "l"(v));
}
__device__ __forceinline__ u64 fma2(u64 a, u64 b, u64 c) {
    u64 d; asm("fma.rn.f32x2 %0, %1, %2, %3;" : "=l"(d) : "l"(a), "l"(b), "l"(c)); return d;
}
__device__ __forceinline__ u64 mul2(u64 a, u64 b) {
    u64 d; asm("mul.rn.f32x2 %0, %1, %2;" : "=l"(d) : "l"(a), "l"(b)); return d;
}
__device__ __forceinline__ u64 add2(u64 a, u64 b) {
    u64 d; asm("add.rn.f32x2 %0, %1, %2;" : "=l"(d) : "l"(a), "l"(b)); return d;
}
__device__ __forceinline__ float ex2f(float x) {
    float r; asm("ex2.approx.f32 %0, %1;" : "=f"(r) : "f"(x)); return r;
}

__global__ __launch_bounds__(NT, 5) void mha_fused_kernel(
    const float* __restrict__ query, const float* __restrict__ key,
    const float* __restrict__ value, const float* __restrict__ wq,
    const float* __restrict__ wk,    const float* __restrict__ wv,
    const float* __restrict__ wo,    float* __restrict__ out, int nbatch)
{
    __shared__ __align__(16) float sw[4][64];        // wq, wk, wv, wo
    __shared__ float ms[SQ][2];                      // sin(pos), cos(pos)
    __shared__ __align__(16) float qs[NB][104][8];   // projected q; reused as attn output
    __shared__ __align__(16) float kvs[NB][KVST];    // row j: k[0..7] then v[0..7]

    const int tid = threadIdx.x;
    const int b0  = blockIdx.x * NB;

    // ---- weights -> shared ----
    for (int i = tid; i < 256; i += NT) {
        int w = i >> 6, e = i & 63;
        const float* src = (w == 0) ? wq : (w == 1) ? wk : (w == 2) ? wv : wo;
        sw[w][e] = src[e];
    }
    // ---- rotary multipliers (Cody-Waite reduction, robust under fast-math) ----
    if (tid < SQ) {
        float x = (float)tid;
        float k = rintf(x * 0.15915494309189535f);
        float r = fmaf(-k, 6.28125f, x);
        r = fmaf(-k, 0.0019353071795864769f, r);
        float s, c; sincosf(r, &s, &c);
        ms[tid][0] = s; ms[tid][1] = c;
    }
    // ---- zero q padding rows 102,103 per batch ----
    if (tid < NB * 16) {
        int nb = tid >> 4;
        (&qs[nb][102][0])[tid & 15] = 0.f;
    }
    __syncthreads();

    // ---- projections + rotary (raw rows streamed from global through L1) ----
    // exp arg = (q.k)*0.5 -> exp2((q.k)*0.5*log2e); fold C into q projection.
    const float C = 0.72134752044448169f;  // 0.5 * log2(e)
    for (int nb = 0; nb < NB; nb++) {
        int b = b0 + nb;
        if (b >= nbatch) break;
        for (int i = tid; i < 1632; i += NT) {
            if (i < 816) {
                int t   = (i >= 408) ? 1 : 0;        // 0 = q, 1 = k
                int rem = i - t * 408;
                int s   = rem >> 2;
                int p   = rem & 3;                   // output pair (head = p>>1)
                const float* src = t ? key : query;
                const float4* row = (const float4*)(src + b * 816 + s * 8);
                float4 f0 = row[0], f1 = row[1];
                const float* w0 = &sw[t][(2 * p) * 8];
                const float* w1 = w0 + 8;
                float d0, d1;
                d0 = f0.x*w0[0]; d1 = f0.x*w1[0];
                d0 = fmaf(f0.y, w0[1], d0); d1 = fmaf(f0.y, w1[1], d1);
                d0 = fmaf(f0.z, w0[2], d0); d1 = fmaf(f0.z, w1[2], d1);
                d0 = fmaf(f0.w, w0[3], d0); d1 = fmaf(f0.w, w1[3], d1);
                d0 = fmaf(f1.x, w0[4], d0); d1 = fmaf(f1.x, w1[4], d1);
                d0 = fmaf(f1.y, w0[5], d0); d1 = fmaf(f1.y, w1[5], d1);
                d0 = fmaf(f1.z, w0[6], d0); d1 = fmaf(f1.z, w1[6], d1);
                d0 = fmaf(f1.w, w0[7], d0); d1 = fmaf(f1.w, w1[7], d1);
                float m = ms[s][p >> 1];
                if (t == 0) {
                    float mm = m * C;
                    qs[nb][s][2*p]   = (d0 - d1) * mm;
                    qs[nb][s][2*p+1] = (d1 + d0) * mm;
                } else {
                    kvs[nb][s*16 + 2*p]     = (d0 - d1) * m;
                    kvs[nb][s*16 + 2*p + 1] = (d1 + d0) * m;
                }
            } else {
                int idx = i - 816;
                int s = idx >> 3;
                int j = idx & 7;
                const float4* row = (const float4*)(value + b * 816 + s * 8);
                float4 f0 = row[0], f1 = row[1];
                const float* w = &sw[2][j * 8];
                float d;
                d = f0.x*w[0];
                d = fmaf(f0.y, w[1], d); d = fmaf(f0.z, w[2], d);
                d = fmaf(f0.w, w[3], d); d = fmaf(f1.x, w[4], d);
                d = fmaf(f1.y, w[5], d); d = fmaf(f1.z, w[6], d);
                d = fmaf(f1.w, w[7], d);
                kvs[nb][s*16 + 8 + j] = d;
            }
        }
    }
    __syncthreads();

    // ---- attention: thread = (nb, head, group of 4 queries); single-pass softmax ----
    if (tid < NB * 52) {
        int nb  = tid / 52;
        int rem = tid - nb * 52;
        int h   = (rem >= 26) ? 1 : 0;
        int qg  = rem - h * 26;
        int b   = b0 + nb;
        if (b < nbatch) {
            const int h4 = h * 4;
            const int q0 = qg * 4;
            u64 q01[4], q23[4], axy[4], azw[4];
            #pragma unroll
            for (int i = 0; i < 4; i++) {
                const u64* qp = (const u64*)&qs[nb][q0 + i][h4];
                q01[i] = qp[0];
                q23[i] = qp[1];
                axy[i] = 0ull;
                azw[i] = 0ull;
            }
            u64 sum01 = 0ull, sum23 = 0ull;
            const float* kvb = &kvs[nb][h4];
            #pragma unroll 2
            for (int j = 0; j < SQ; j++) {
                ulonglong2 kk = *(const ulonglong2*)(kvb + j * 16);       // k pair
                ulonglong2 vv = *(const ulonglong2*)(kvb + j * 16 + 8);   // v pair
                float e[4];
                #pragma unroll
                for (int i = 0; i < 4; i++) {
                    u64 d = fma2(q23[i], kk.y, mul2(q01[i], kk.x));
                    float dl, dh; unpack2(d, dl, dh);
                    e[i] = ex2f(dl + dh);
                    u64 e2 = pack2(e[i], e[i]);
                    axy[i] = fma2(e2, vv.x, axy[i]);
                    azw[i] = fma2(e2, vv.y, azw[i]);
                }
                sum01 = add2(sum01, pack2(e[0], e[1]));
                sum23 = add2(sum23, pack2(e[2], e[3]));
            }
            float sm[4];
            unpack2(sum01, sm[0], sm[1]);
            unpack2(sum23, sm[2], sm[3]);
            #pragma unroll
            for (int i = 0; i < 4; i++) {
                float inv = 1.0f / sm[i];
                float x0, x1, x2, x3;
                unpack2(axy[i], x0, x1);
                unpack2(azw[i], x2, x3);
                // write back into qs (q no longer needed; pad rows 102/103 harmless)
                *(float4*)&qs[nb][q0 + i][h4] =
                    make_float4(x0 * inv, x1 * inv, x2 * inv, x3 * inv);
            }
        }
    }
    __syncthreads();

    // ---- output projection: out[s][j] = dot(ao[s], wo[j]); ao lives in qs ----
    for (int nb = 0; nb < NB; nb++) {
        int b = b0 + nb;
        if (b >= nbatch) break;
        for (int i = tid; i < 816; i += NT) {
            int s = i >> 3, j = i & 7;
            const float* x = qs[nb][s];
            const float* w = &sw[3][j * 8];
            float d = 0.f;
            #pragma unroll
            for (int k = 0; k < 8; k++) d = fmaf(x[k], w[k], d);
            out[b * 816 + i] = d;
        }
    }
}

extern "C" void kernel_launch(void* const* d_in, const int* in_sizes, int n_in,
                              void* d_out, int out_size)
{
    const float* query = (const float*)d_in[0];
    const float* key   = (const float*)d_in[1];
    const float* value = (const float*)d_in[2];
    const float* wq    = (const float*)d_in[3];
    const float* wk    = (const float*)d_in[4];
    const float* wv    = (const float*)d_in[5];
    const float* wo    = (const float*)d_in[6];
    float* out = (float*)d_out;

    int nbatch = in_sizes[0] / (SQ * 8);          // 4096
    int grid = (nbatch + NB - 1) / NB;            // 1024
    mha_fused_kernel<<<grid, NT>>>(query, key, value, wq, wk, wv, wo, out, nbatch);
}

// round 11
// speedup vs baseline: 1.1851x; 1.1851x over previous
#include <cuda_runtime.h>

// MultiHeadAttention: B=4096, S=102, HIDDEN=8, HEADS=2, HEAD_DIM=4
// NB=7 batches/CTA, NT=384, dynamic smem padded to 80KB to force 2 CTAs/SM:
// grid=586 over n_conc=296 -> 1.98 waves (both ~full; kills wave-quantization tail).
// Packed f32x2 everywhere: projections use x-pair x w-pair dots (no pack MOVs).

#define SQ    102
#define NB    7
#define NT    384
#define KVST  1640                 // floats per batch in kvs: stride mod 32 = 8
#define SMEM_BYTES 81920           // pad: 2 CTAs fit (160K <= 227K), 3 don't

typedef unsigned long long u64;

__device__ __forceinline__ u64 pack2(float lo, float hi) {
    u64 r; asm("mov.b64 %0, {%1, %2};" : "=l"(r) : "f"(lo), "f"(hi)); return r;
}
__device__ __forceinline__ void unpack2(u64 v, float& lo, float& hi) {
    asm("mov.b64 {%0, %1}, %2;" : "=f"(lo), "=f"(hi) : "l"(v));
}
__device__ __forceinline__ u64 fma2(u64 a, u64 b, u64 c) {
    u64 d; asm("fma.rn.f32x2 %0, %1, %2, %3;" : "=l"(d) : "l"(a), "l"(b), "l"(c)); return d;
}
__device__ __forceinline__ u64 mul2(u64 a, u64 b) {
    u64 d; asm("mul.rn.f32x2 %0, %1, %2;" : "=l"(d) : "l"(a), "l"(b)); return d;
}
__device__ __forceinline__ u64 add2(u64 a, u64 b) {
    u64 d; asm("add.rn.f32x2 %0, %1, %2;" : "=l"(d) : "l"(a), "l"(b)); return d;
}
__device__ __forceinline__ float ex2f(float x) {
    float r; asm("ex2.approx.f32 %0, %1;" : "=f"(r) : "f"(x)); return r;
}

// dual 8-dot: d0 = x . w[row 2p], d1 = x . w[row 2p+1]; w rows are 4 u64 each, adjacent.
__device__ __forceinline__ void dual_dot8(const u64* w, u64 xax, u64 xay,
                                          u64 xbx, u64 xby, float& d0, float& d1)
{
    u64 a0 = mul2(xax, w[0]);
    a0 = fma2(xay, w[1], a0);
    a0 = fma2(xbx, w[2], a0);
    a0 = fma2(xby, w[3], a0);
    u64 a1 = mul2(xax, w[4]);
    a1 = fma2(xay, w[5], a1);
    a1 = fma2(xbx, w[6], a1);
    a1 = fma2(xby, w[7], a1);
    float l0, h0, l1, h1;
    unpack2(a0, l0, h0); unpack2(a1, l1, h1);
    d0 = l0 + h0; d1 = l1 + h1;
}

__global__ __launch_bounds__(NT) void mha_fused_kernel(
    const float* __restrict__ query, const float* __restrict__ key,
    const float* __restrict__ value, const float* __restrict__ wq,
    const float* __restrict__ wk,    const float* __restrict__ wv,
    const float* __restrict__ wo,    float* __restrict__ out, int nbatch)
{
    extern __shared__ __align__(16) char smraw[];
    float (*sw)[64]      = (float (*)[64])smraw;                    // [4][64]   = 1024 B
    float (*ms)[2]       = (float (*)[2])(smraw + 1024);            // [102][2]  =  816 B
    float (*qs)[104][8]  = (float (*)[104][8])(smraw + 1856);       // [NB][104][8] = 23296 B
    float (*kvs)[KVST]   = (float (*)[KVST])(smraw + 25152);        // [NB][1640]   = 45920 B

    const int tid = threadIdx.x;
    const int b0  = blockIdx.x * NB;

    // ---- weights -> shared ----
    for (int i = tid; i < 256; i += NT) {
        int w = i >> 6, e = i & 63;
        const float* src = (w == 0) ? wq : (w == 1) ? wk : (w == 2) ? wv : wo;
        sw[w][e] = src[e];
    }
    // ---- rotary multipliers (Cody-Waite reduction, robust under fast-math) ----
    if (tid < SQ) {
        float x = (float)tid;
        float k = rintf(x * 0.15915494309189535f);
        float r = fmaf(-k, 6.28125f, x);
        r = fmaf(-k, 0.0019353071795864769f, r);
        float s, c; sincosf(r, &s, &c);
        ms[tid][0] = s; ms[tid][1] = c;
    }
    // ---- zero q padding rows 102,103 per batch ----
    if (tid < NB * 16) {
        int nb = tid >> 4;
        (&qs[nb][102][0])[tid & 15] = 0.f;
    }
    __syncthreads();

    // ---- projections + rotary; one thread = one full row (8 outputs) ----
    // exp arg = (q.k)*0.5 -> exp2((q.k)*0.5*log2e); fold C into q projection.
    const float C = 0.72134752044448169f;   // 0.5 * log2(e)
    for (int i = tid; i < NB * 306; i += NT) {
        int nb  = i / 306;
        int rem = i - nb * 306;
        int b   = b0 + nb;
        if (b >= nbatch) continue;
        int t = rem / 102;                  // 0=q, 1=k, 2=v
        int s = rem - t * 102;
        const float* src = (t == 0) ? query : (t == 1) ? key : value;
        const ulonglong2* xr = (const ulonglong2*)(src + (size_t)b * 816 + s * 8);
        ulonglong2 xa = xr[0], xb = xr[1];
        float o[8];
        if (t < 2) {
            float msin = ms[s][0], mcos = ms[s][1];
            if (t == 0) { msin *= C; mcos *= C; }
            #pragma unroll
            for (int p = 0; p < 4; p++) {
                const u64* w = (const u64*)&sw[t][(2 * p) * 8];
                float d0, d1;
                dual_dot8(w, xa.x, xa.y, xb.x, xb.y, d0, d1);
                float m = (p < 2) ? msin : mcos;     // head0 -> sin, head1 -> cos
                o[2*p]   = (d0 - d1) * m;
                o[2*p+1] = (d1 + d0) * m;
            }
            float* dst = (t == 0) ? &qs[nb][s][0] : &kvs[nb][s * 16];
            *(float4*)dst       = make_float4(o[0], o[1], o[2], o[3]);
            *(float4*)(dst + 4) = make_float4(o[4], o[5], o[6], o[7]);
        } else {
            #pragma unroll
            for (int p = 0; p < 4; p++) {
                const u64* w = (const u64*)&sw[2][(2 * p) * 8];
                dual_dot8(w, xa.x, xa.y, xb.x, xb.y, o[2*p], o[2*p+1]);
            }
            float* dst = &kvs[nb][s * 16 + 8];
            *(float4*)dst       = make_float4(o[0], o[1], o[2], o[3]);
            *(float4*)(dst + 4) = make_float4(o[4], o[5], o[6], o[7]);
        }
    }
    __syncthreads();

    // ---- attention: thread = (nb, head, group of 4 queries); single-pass softmax ----
    if (tid < NB * 52) {
        int nb  = tid / 52;
        int rem = tid - nb * 52;
        int h   = (rem >= 26) ? 1 : 0;
        int qg  = rem - h * 26;
        int b   = b0 + nb;
        if (b < nbatch) {
            const int h4 = h * 4;
            const int q0 = qg * 4;
            u64 q01[4], q23[4], axy[4], azw[4];
            #pragma unroll
            for (int i = 0; i < 4; i++) {
                const u64* qp = (const u64*)&qs[nb][q0 + i][h4];
                q01[i] = qp[0];
                q23[i] = qp[1];
                axy[i] = 0ull;
                azw[i] = 0ull;
            }
            u64 sum01 = 0ull, sum23 = 0ull;
            const float* kvb = &kvs[nb][h4];
            #pragma unroll 2
            for (int j = 0; j < SQ; j++) {
                ulonglong2 kk = *(const ulonglong2*)(kvb + j * 16);       // k pair
                ulonglong2 vv = *(const ulonglong2*)(kvb + j * 16 + 8);   // v pair
                float e[4];
                #pragma unroll
                for (int i = 0; i < 4; i++) {
                    u64 d = fma2(q23[i], kk.y, mul2(q01[i], kk.x));
                    float dl, dh; unpack2(d, dl, dh);
                    e[i] = ex2f(dl + dh);
                    u64 e2 = pack2(e[i], e[i]);
                    axy[i] = fma2(e2, vv.x, axy[i]);
                    azw[i] = fma2(e2, vv.y, azw[i]);
                }
                sum01 = add2(sum01, pack2(e[0], e[1]));
                sum23 = add2(sum23, pack2(e[2], e[3]));
            }
            float sm[4];
            unpack2(sum01, sm[0], sm[1]);
            unpack2(sum23, sm[2], sm[3]);
            #pragma unroll
            for (int i = 0; i < 4; i++) {
                float inv = 1.0f / sm[i];
                float x0, x1, x2, x3;
                unpack2(axy[i], x0, x1);
                unpack2(azw[i], x2, x3);
                // write back into qs (q no longer needed; pad rows 102/103 harmless)
                *(float4*)&qs[nb][q0 + i][h4] =
                    make_float4(x0 * inv, x1 * inv, x2 * inv, x3 * inv);
            }
        }
    }
    __syncthreads();

    // ---- output projection: one thread = one row; ao lives in qs ----
    for (int i = tid; i < NB * SQ; i += NT) {
        int nb = i / 102;
        int s  = i - nb * 102;
        int b  = b0 + nb;
        if (b >= nbatch) continue;
        const ulonglong2* xr = (const ulonglong2*)&qs[nb][s][0];
        ulonglong2 xa = xr[0], xb = xr[1];
        float o[8];
        #pragma unroll
        for (int p = 0; p < 4; p++) {
            const u64* w = (const u64*)&sw[3][(2 * p) * 8];
            dual_dot8(w, xa.x, xa.y, xb.x, xb.y, o[2*p], o[2*p+1]);
        }
        float4* dst = (float4*)(out + (size_t)b * 816 + s * 8);
        dst[0] = make_float4(o[0], o[1], o[2], o[3]);
        dst[1] = make_float4(o[4], o[5], o[6], o[7]);
    }
}

extern "C" void kernel_launch(void* const* d_in, const int* in_sizes, int n_in,
                              void* d_out, int out_size)
{
    const float* query = (const float*)d_in[0];
    const float* key   = (const float*)d_in[1];
    const float* value = (const float*)d_in[2];
    const float* wq    = (const float*)d_in[3];
    const float* wk    = (const float*)d_in[4];
    const float* wv    = (const float*)d_in[5];
    const float* wo    = (const float*)d_in[6];
    float* out = (float*)d_out;

    cudaFuncSetAttribute(mha_fused_kernel,
                         cudaFuncAttributeMaxDynamicSharedMemorySize, SMEM_BYTES);

    int nbatch = in_sizes[0] / (SQ * 8);            // 4096
    int grid = (nbatch + NB - 1) / NB;              // 586
    mha_fused_kernel<<<grid, NT, SMEM_BYTES>>>(query, key, value, wq, wk, wv, wo,
                                               out, nbatch);
}

// round 12
// speedup vs baseline: 1.1857x; 1.0005x over previous
#include <cuda_runtime.h>

// MultiHeadAttention: B=4096, S=102, HIDDEN=8, HEADS=2, HEAD_DIM=4
// NB=7 batches/CTA, NT=384, dynamic smem padded to 80KB to force 2 CTAs/SM:
// grid=586 over n_conc=296 -> 1.98 waves (both ~full; kills wave-quantization tail).
// Packed f32x2 everywhere: projections use x-pair x w-pair dots (no pack MOVs).

#define SQ    102
#define NB    7
#define NT    384
#define KVST  1640                 // floats per batch in kvs: stride mod 32 = 8
#define SMEM_BYTES 81920           // pad: 2 CTAs fit (160K <= 227K), 3 don't

typedef unsigned long long u64;

__device__ __forceinline__ u64 pack2(float lo, float hi) {
    u64 r; asm("mov.b64 %0, {%1, %2};" : "=l"(r) : "f"(lo), "f"(hi)); return r;
}
__device__ __forceinline__ void unpack2(u64 v, float& lo, float& hi) {
    asm("mov.b64 {%0, %1}, %2;" : "=f"(lo), "=f"(hi) : "l"(v));
}
__device__ __forceinline__ u64 fma2(u64 a, u64 b, u64 c) {
    u64 d; asm("fma.rn.f32x2 %0, %1, %2, %3;" : "=l"(d) : "l"(a), "l"(b), "l"(c)); return d;
}
__device__ __forceinline__ u64 mul2(u64 a, u64 b) {
    u64 d; asm("mul.rn.f32x2 %0, %1, %2;" : "=l"(d) : "l"(a), "l"(b)); return d;
}
__device__ __forceinline__ u64 add2(u64 a, u64 b) {
    u64 d; asm("add.rn.f32x2 %0, %1, %2;" : "=l"(d) : "l"(a), "l"(b)); return d;
}
__device__ __forceinline__ float ex2f(float x) {
    float r; asm("ex2.approx.f32 %0, %1;" : "=f"(r) : "f"(x)); return r;
}

// dual 8-dot: d0 = x . w[row 2p], d1 = x . w[row 2p+1]; w rows are 4 u64 each, adjacent.
__device__ __forceinline__ void dual_dot8(const u64* w, u64 xax, u64 xay,
                                          u64 xbx, u64 xby, float& d0, float& d1)
{
    u64 a0 = mul2(xax, w[0]);
    a0 = fma2(xay, w[1], a0);
    a0 = fma2(xbx, w[2], a0);
    a0 = fma2(xby, w[3], a0);
    u64 a1 = mul2(xax, w[4]);
    a1 = fma2(xay, w[5], a1);
    a1 = fma2(xbx, w[6], a1);
    a1 = fma2(xby, w[7], a1);
    float l0, h0, l1, h1;
    unpack2(a0, l0, h0); unpack2(a1, l1, h1);
    d0 = l0 + h0; d1 = l1 + h1;
}

__global__ __launch_bounds__(NT) void mha_fused_kernel(
    const float* __restrict__ query, const float* __restrict__ key,
    const float* __restrict__ value, const float* __restrict__ wq,
    const float* __restrict__ wk,    const float* __restrict__ wv,
    const float* __restrict__ wo,    float* __restrict__ out, int nbatch)
{
    extern __shared__ __align__(16) char smraw[];
    float (*sw)[64]      = (float (*)[64])smraw;                    // [4][64]   = 1024 B
    float (*ms)[2]       = (float (*)[2])(smraw + 1024);            // [102][2]  =  816 B
    float (*qs)[104][8]  = (float (*)[104][8])(smraw + 1856);       // [NB][104][8] = 23296 B
    float (*kvs)[KVST]   = (float (*)[KVST])(smraw + 25152);        // [NB][1640]   = 45920 B

    const int tid = threadIdx.x;
    const int b0  = blockIdx.x * NB;

    // ---- weights -> shared ----
    for (int i = tid; i < 256; i += NT) {
        int w = i >> 6, e = i & 63;
        const float* src = (w == 0) ? wq : (w == 1) ? wk : (w == 2) ? wv : wo;
        sw[w][e] = src[e];
    }
    // ---- rotary multipliers (Cody-Waite reduction, robust under fast-math) ----
    if (tid < SQ) {
        float x = (float)tid;
        float k = rintf(x * 0.15915494309189535f);
        float r = fmaf(-k, 6.28125f, x);
        r = fmaf(-k, 0.0019353071795864769f, r);
        float s, c; sincosf(r, &s, &c);
        ms[tid][0] = s; ms[tid][1] = c;
    }
    // ---- zero q padding rows 102,103 per batch ----
    if (tid < NB * 16) {
        int nb = tid >> 4;
        (&qs[nb][102][0])[tid & 15] = 0.f;
    }
    __syncthreads();

    // ---- projections + rotary; one thread = one full row (8 outputs) ----
    // exp arg = (q.k)*0.5 -> exp2((q.k)*0.5*log2e); fold C into q projection.
    const float C = 0.72134752044448169f;   // 0.5 * log2(e)
    for (int i = tid; i < NB * 306; i += NT) {
        int nb  = i / 306;
        int rem = i - nb * 306;
        int b   = b0 + nb;
        if (b >= nbatch) continue;
        int t = rem / 102;                  // 0=q, 1=k, 2=v
        int s = rem - t * 102;
        const float* src = (t == 0) ? query : (t == 1) ? key : value;
        const ulonglong2* xr = (const ulonglong2*)(src + (size_t)b * 816 + s * 8);
        ulonglong2 xa = xr[0], xb = xr[1];
        float o[8];
        if (t < 2) {
            float msin = ms[s][0], mcos = ms[s][1];
            if (t == 0) { msin *= C; mcos *= C; }
            #pragma unroll
            for (int p = 0; p < 4; p++) {
                const u64* w = (const u64*)&sw[t][(2 * p) * 8];
                float d0, d1;
                dual_dot8(w, xa.x, xa.y, xb.x, xb.y, d0, d1);
                float m = (p < 2) ? msin : mcos;     // head0 -> sin, head1 -> cos
                o[2*p]   = (d0 - d1) * m;
                o[2*p+1] = (d1 + d0) * m;
            }
            float* dst = (t == 0) ? &qs[nb][s][0] : &kvs[nb][s * 16];
            *(float4*)dst       = make_float4(o[0], o[1], o[2], o[3]);
            *(float4*)(dst + 4) = make_float4(o[4], o[5], o[6], o[7]);
        } else {
            #pragma unroll
            for (int p = 0; p < 4; p++) {
                const u64* w = (const u64*)&sw[2][(2 * p) * 8];
                dual_dot8(w, xa.x, xa.y, xb.x, xb.y, o[2*p], o[2*p+1]);
            }
            float* dst = &kvs[nb][s * 16 + 8];
            *(float4*)dst       = make_float4(o[0], o[1], o[2], o[3]);
            *(float4*)(dst + 4) = make_float4(o[4], o[5], o[6], o[7]);
        }
    }
    __syncthreads();

    // ---- attention: thread = (nb, head, group of 4 queries); single-pass softmax ----
    if (tid < NB * 52) {
        int nb  = tid / 52;
        int rem = tid - nb * 52;
        int h   = (rem >= 26) ? 1 : 0;
        int qg  = rem - h * 26;
        int b   = b0 + nb;
        if (b < nbatch) {
            const int h4 = h * 4;
            const int q0 = qg * 4;
            u64 q01[4], q23[4], axy[4], azw[4];
            #pragma unroll
            for (int i = 0; i < 4; i++) {
                const u64* qp = (const u64*)&qs[nb][q0 + i][h4];
                q01[i] = qp[0];
                q23[i] = qp[1];
                axy[i] = 0ull;
                azw[i] = 0ull;
            }
            u64 sum01 = 0ull, sum23 = 0ull;
            const float* kvb = &kvs[nb][h4];
            #pragma unroll 2
            for (int j = 0; j < SQ; j++) {
                ulonglong2 kk = *(const ulonglong2*)(kvb + j * 16);       // k pair
                ulonglong2 vv = *(const ulonglong2*)(kvb + j * 16 + 8);   // v pair
                float e[4];
                #pragma unroll
                for (int i = 0; i < 4; i++) {
                    u64 d = fma2(q23[i], kk.y, mul2(q01[i], kk.x));
                    float dl, dh; unpack2(d, dl, dh);
                    e[i] = ex2f(dl + dh);
                    u64 e2 = pack2(e[i], e[i]);
                    axy[i] = fma2(e2, vv.x, axy[i]);
                    azw[i] = fma2(e2, vv.y, azw[i]);
                }
                sum01 = add2(sum01, pack2(e[0], e[1]));
                sum23 = add2(sum23, pack2(e[2], e[3]));
            }
            float sm[4];
            unpack2(sum01, sm[0], sm[1]);
            unpack2(sum23, sm[2], sm[3]);
            #pragma unroll
            for (int i = 0; i < 4; i++) {
                float inv = 1.0f / sm[i];
                float x0, x1, x2, x3;
                unpack2(axy[i], x0, x1);
                unpack2(azw[i], x2, x3);
                // write back into qs (q no longer needed; pad rows 102/103 harmless)
                *(float4*)&qs[nb][q0 + i][h4] =
                    make_float4(x0 * inv, x1 * inv, x2 * inv, x3 * inv);
            }
        }
    }
    __syncthreads();

    // ---- output projection: one thread = one row; ao lives in qs ----
    for (int i = tid; i < NB * SQ; i += NT) {
        int nb = i / 102;
        int s  = i - nb * 102;
        int b  = b0 + nb;
        if (b >= nbatch) continue;
        const ulonglong2* xr = (const ulonglong2*)&qs[nb][s][0];
        ulonglong2 xa = xr[0], xb = xr[1];
        float o[8];
        #pragma unroll
        for (int p = 0; p < 4; p++) {
            const u64* w = (const u64*)&sw[3][(2 * p) * 8];
            dual_dot8(w, xa.x, xa.y, xb.x, xb.y, o[2*p], o[2*p+1]);
        }
        float4* dst = (float4*)(out + (size_t)b * 816 + s * 8);
        dst[0] = make_float4(o[0], o[1], o[2], o[3]);
        dst[1] = make_float4(o[4], o[5], o[6], o[7]);
    }
}

extern "C" void kernel_launch(void* const* d_in, const int* in_sizes, int n_in,
                              void* d_out, int out_size)
{
    const float* query = (const float*)d_in[0];
    const float* key   = (const float*)d_in[1];
    const float* value = (const float*)d_in[2];
    const float* wq    = (const float*)d_in[3];
    const float* wk    = (const float*)d_in[4];
    const float* wv    = (const float*)d_in[5];
    const float* wo    = (const float*)d_in[6];
    float* out = (float*)d_out;

    cudaFuncSetAttribute(mha_fused_kernel,
                         cudaFuncAttributeMaxDynamicSharedMemorySize, SMEM_BYTES);

    int nbatch = in_sizes[0] / (SQ * 8);            // 4096
    int grid = (nbatch + NB - 1) / NB;              // 586
    mha_fused_kernel<<<grid, NT, SMEM_BYTES>>>(query, key, value, wq, wk, wv, wo,
                                               out, nbatch);
}

// round 13
// speedup vs baseline: 1.2608x; 1.0633x over previous
#include <cuda_runtime.h>

// MultiHeadAttention: B=4096, S=102, HIDDEN=8, HEADS=2, HEAD_DIM=4
// NB=7 batches/CTA, NT=512, QB=3 (102=3*34 exact), smem padded to 80KB ->
// 2 CTAs/SM, 32 warps/SM, grid=586 over n_conc=296 -> 1.98 waves.
// Packed f32x2 math throughout.

#define SQ    102
#define NB    7
#define NT    512
#define KVST  1640                 // floats per batch in kvs
#define SMEM_BYTES 81920           // pad: exactly 2 CTAs/SM

typedef unsigned long long u64;

__device__ __forceinline__ u64 pack2(float lo, float hi) {
    u64 r; asm("mov.b64 %0, {%1, %2};" : "=l"(r) : "f"(lo), "f"(hi)); return r;
}
__device__ __forceinline__ void unpack2(u64 v, float& lo, float& hi) {
    asm("mov.b64 {%0, %1}, %2;" : "=f"(lo), "=f"(hi) : "l"(v));
}
__device__ __forceinline__ u64 fma2(u64 a, u64 b, u64 c) {
    u64 d; asm("fma.rn.f32x2 %0, %1, %2, %3;" : "=l"(d) : "l"(a), "l"(b), "l"(c)); return d;
}
__device__ __forceinline__ u64 mul2(u64 a, u64 b) {
    u64 d; asm("mul.rn.f32x2 %0, %1, %2;" : "=l"(d) : "l"(a), "l"(b)); return d;
}
__device__ __forceinline__ u64 add2(u64 a, u64 b) {
    u64 d; asm("add.rn.f32x2 %0, %1, %2;" : "=l"(d) : "l"(a), "l"(b)); return d;
}
__device__ __forceinline__ float ex2f(float x) {
    float r; asm("ex2.approx.f32 %0, %1;" : "=f"(r) : "f"(x)); return r;
}

// dual 8-dot: d0 = x . w[row 2p], d1 = x . w[row 2p+1]; w rows are 4 u64 each.
__device__ __forceinline__ void dual_dot8(const u64* w, u64 xax, u64 xay,
                                          u64 xbx, u64 xby, float& d0, float& d1)
{
    u64 a0 = mul2(xax, w[0]);
    a0 = fma2(xay, w[1], a0);
    a0 = fma2(xbx, w[2], a0);
    a0 = fma2(xby, w[3], a0);
    u64 a1 = mul2(xax, w[4]);
    a1 = fma2(xay, w[5], a1);
    a1 = fma2(xbx, w[6], a1);
    a1 = fma2(xby, w[7], a1);
    float l0, h0, l1, h1;
    unpack2(a0, l0, h0); unpack2(a1, l1, h1);
    d0 = l0 + h0; d1 = l1 + h1;
}

__global__ __launch_bounds__(NT, 2) void mha_fused_kernel(
    const float* __restrict__ query, const float* __restrict__ key,
    const float* __restrict__ value, const float* __restrict__ wq,
    const float* __restrict__ wk,    const float* __restrict__ wv,
    const float* __restrict__ wo,    float* __restrict__ out, int nbatch)
{
    extern __shared__ __align__(16) char smraw[];
    float (*sw)[64]      = (float (*)[64])smraw;                    // [4][64]      1024 B
    float (*ms)[2]       = (float (*)[2])(smraw + 1024);            // [102][2]      816 B
    float (*qs)[SQ][8]   = (float (*)[SQ][8])(smraw + 1856);        // [NB][102][8] 22848 B
    float (*kvs)[KVST]   = (float (*)[KVST])(smraw + 24704);        // [NB][1640]   45920 B

    const int tid = threadIdx.x;
    const int b0  = blockIdx.x * NB;

    // ---- weights -> shared ----
    if (tid < 256) {
        int w = tid >> 6, e = tid & 63;
        const float* src = (w == 0) ? wq : (w == 1) ? wk : (w == 2) ? wv : wo;
        sw[w][e] = src[e];
    }
    // ---- rotary multipliers (Cody-Waite reduction, robust under fast-math) ----
    if (tid >= 256 && tid < 256 + SQ) {
        float x = (float)(tid - 256);
        float k = rintf(x * 0.15915494309189535f);
        float r = fmaf(-k, 6.28125f, x);
        r = fmaf(-k, 0.0019353071795864769f, r);
        float s, c; sincosf(r, &s, &c);
        ms[tid - 256][0] = s; ms[tid - 256][1] = c;
    }
    __syncthreads();

    // ---- projections + rotary; one thread = one full row (8 outputs) ----
    // exp arg = (q.k)*0.5 -> exp2((q.k)*0.5*log2e); fold C into q projection.
    const float C = 0.72134752044448169f;   // 0.5 * log2(e)
    for (int i = tid; i < NB * 306; i += NT) {
        int nb  = i / 306;
        int rem = i - nb * 306;
        int b   = b0 + nb;
        if (b >= nbatch) continue;
        int t = rem / 102;                  // 0=q, 1=k, 2=v
        int s = rem - t * 102;
        const float* src = (t == 0) ? query : (t == 1) ? key : value;
        const ulonglong2* xr = (const ulonglong2*)(src + (size_t)b * 816 + s * 8);
        ulonglong2 xa = xr[0], xb = xr[1];
        float o[8];
        if (t < 2) {
            float msin = ms[s][0], mcos = ms[s][1];
            if (t == 0) { msin *= C; mcos *= C; }
            #pragma unroll
            for (int p = 0; p < 4; p++) {
                const u64* w = (const u64*)&sw[t][(2 * p) * 8];
                float d0, d1;
                dual_dot8(w, xa.x, xa.y, xb.x, xb.y, d0, d1);
                float m = (p < 2) ? msin : mcos;     // head0 -> sin, head1 -> cos
                o[2*p]   = (d0 - d1) * m;
                o[2*p+1] = (d1 + d0) * m;
            }
            float* dst = (t == 0) ? &qs[nb][s][0] : &kvs[nb][s * 16];
            *(float4*)dst       = make_float4(o[0], o[1], o[2], o[3]);
            *(float4*)(dst + 4) = make_float4(o[4], o[5], o[6], o[7]);
        } else {
            #pragma unroll
            for (int p = 0; p < 4; p++) {
                const u64* w = (const u64*)&sw[2][(2 * p) * 8];
                dual_dot8(w, xa.x, xa.y, xb.x, xb.y, o[2*p], o[2*p+1]);
            }
            float* dst = &kvs[nb][s * 16 + 8];
            *(float4*)dst       = make_float4(o[0], o[1], o[2], o[3]);
            *(float4*)(dst + 4) = make_float4(o[4], o[5], o[6], o[7]);
        }
    }
    __syncthreads();

    // ---- attention: thread = (nb, head, group of 3 queries); single-pass softmax ----
    if (tid < NB * 68) {
        int nb  = tid / 68;
        int rem = tid - nb * 68;
        int h   = (rem >= 34) ? 1 : 0;
        int qg  = rem - h * 34;
        int b   = b0 + nb;
        if (b < nbatch) {
            const int h4 = h * 4;
            const int q0 = qg * 3;
            u64 q01[3], q23[3], axy[3], azw[3];
            #pragma unroll
            for (int i = 0; i < 3; i++) {
                const u64* qp = (const u64*)&qs[nb][q0 + i][h4];
                q01[i] = qp[0];
                q23[i] = qp[1];
                axy[i] = 0ull;
                azw[i] = 0ull;
            }
            u64 sum01 = 0ull;
            float sum2 = 0.f;
            const float* kvb = &kvs[nb][h4];
            #pragma unroll 2
            for (int j = 0; j < SQ; j++) {
                ulonglong2 kk = *(const ulonglong2*)(kvb + j * 16);       // k pair
                ulonglong2 vv = *(const ulonglong2*)(kvb + j * 16 + 8);   // v pair
                float e[3];
                #pragma unroll
                for (int i = 0; i < 3; i++) {
                    u64 d = fma2(q23[i], kk.y, mul2(q01[i], kk.x));
                    float dl, dh; unpack2(d, dl, dh);
                    e[i] = ex2f(dl + dh);
                    u64 e2 = pack2(e[i], e[i]);
                    axy[i] = fma2(e2, vv.x, axy[i]);
                    azw[i] = fma2(e2, vv.y, azw[i]);
                }
                sum01 = add2(sum01, pack2(e[0], e[1]));
                sum2 += e[2];
            }
            float sm[3];
            unpack2(sum01, sm[0], sm[1]);
            sm[2] = sum2;
            #pragma unroll
            for (int i = 0; i < 3; i++) {
                float inv = 1.0f / sm[i];
                float x0, x1, x2, x3;
                unpack2(axy[i], x0, x1);
                unpack2(azw[i], x2, x3);
                // write back into qs (q no longer needed)
                *(float4*)&qs[nb][q0 + i][h4] =
                    make_float4(x0 * inv, x1 * inv, x2 * inv, x3 * inv);
            }
        }
    }
    __syncthreads();

    // ---- output projection: one thread = one row; ao lives in qs ----
    for (int i = tid; i < NB * SQ; i += NT) {
        int nb = i / 102;
        int s  = i - nb * 102;
        int b  = b0 + nb;
        if (b >= nbatch) continue;
        const ulonglong2* xr = (const ulonglong2*)&qs[nb][s][0];
        ulonglong2 xa = xr[0], xb = xr[1];
        float o[8];
        #pragma unroll
        for (int p = 0; p < 4; p++) {
            const u64* w = (const u64*)&sw[3][(2 * p) * 8];
            dual_dot8(w, xa.x, xa.y, xb.x, xb.y, o[2*p], o[2*p+1]);
        }
        float4* dst = (float4*)(out + (size_t)b * 816 + s * 8);
        dst[0] = make_float4(o[0], o[1], o[2], o[3]);
        dst[1] = make_float4(o[4], o[5], o[6], o[7]);
    }
}

extern "C" void kernel_launch(void* const* d_in, const int* in_sizes, int n_in,
                              void* d_out, int out_size)
{
    const float* query = (const float*)d_in[0];
    const float* key   = (const float*)d_in[1];
    const float* value = (const float*)d_in[2];
    const float* wq    = (const float*)d_in[3];
    const float* wk    = (const float*)d_in[4];
    const float* wv    = (const float*)d_in[5];
    const float* wo    = (const float*)d_in[6];
    float* out = (float*)d_out;

    cudaFuncSetAttribute(mha_fused_kernel,
                         cudaFuncAttributeMaxDynamicSharedMemorySize, SMEM_BYTES);

    int nbatch = in_sizes[0] / (SQ * 8);            // 4096
    int grid = (nbatch + NB - 1) / NB;              // 586
    mha_fused_kernel<<<grid, NT, SMEM_BYTES>>>(query, key, value, wq, wk, wv, wo,
                                               out, nbatch);
}